// round 8
// baseline (speedup 1.0000x reference)
#include <cuda_runtime.h>
#include <cstdint>

// ============================================================================
// ShiftConv as gather-GEMM, fp16 mma.sync m16n8k16 (fp32 accum):
//   out[n,d,y,x] = sum_c x[n,c,y+sh[c],x+sw[c]] * W[c,d] + bias[d]
// M = 131072 pixels, K = 256, N = 256.
// CTA 64(M) x 256(N), 256 thr (8 warps, warp tile 64x32), K chunk 32 x 8,
// double-buffered, ~42 KB smem -> TWO independent CTAs per SM for
// phase-shifted latency hiding. 1 LDS.128 = full mma operand.
// ============================================================================

#define CIN   256
#define NOUT  256
#define HW    4096

// A stage: f4[2 ks][4 g][8 r][4 a'] = 256 f4 = 4 KB / buffer
#define A_F4   256
// B stage: f4[256 n][4 a'] = 1024 f4 = 16 KB / buffer (both k-steps packed)
#define B_F4   1024
#define NCH    8

__device__ float4 g_wp[NCH * B_F4];   // packed fp16 weight, 128 KB

static __device__ __forceinline__ uint32_t f16x2(float hi, float lo) {
    uint32_t d;
    asm("cvt.rn.f16x2.f32 %0, %1, %2;" : "=r"(d) : "f"(hi), "f"(lo));
    return d;
}

// --- prep: pack W into fp16 f4 slots, fragment-paired + pre-swizzled ---
// f4 index: s(8)|n(256)|a'(4); a = a' ^ ((n>>1)&3); c0 = s*32 + a*2
// words: w0={W[c0],W[c0+1]}, w1={+8,+9}, w2={+16,+17}, w3={+24,+25} (all @ n)
__global__ void pack_w_kernel(const float* __restrict__ w) {
    int t = blockIdx.x * 256 + threadIdx.x;     // 0..8191
    int ap = t & 3;
    int n  = (t >> 2) & 255;
    int s  = t >> 10;
    int a  = ap ^ ((n >> 1) & 3);
    int c0 = s * 32 + a * 2;
    float4 v;
    v.x = __uint_as_float(f16x2(w[(c0 +  1) * NOUT + n], w[(c0     ) * NOUT + n]));
    v.y = __uint_as_float(f16x2(w[(c0 +  9) * NOUT + n], w[(c0 +  8) * NOUT + n]));
    v.z = __uint_as_float(f16x2(w[(c0 + 17) * NOUT + n], w[(c0 + 16) * NOUT + n]));
    v.w = __uint_as_float(f16x2(w[(c0 + 25) * NOUT + n], w[(c0 + 24) * NOUT + n]));
    g_wp[t] = v;
}

static __device__ __forceinline__ void mma_f16(float* c, uint32_t a0, uint32_t a1,
                                               uint32_t a2, uint32_t a3,
                                               uint32_t b0, uint32_t b1) {
    asm volatile(
        "mma.sync.aligned.m16n8k16.row.col.f32.f16.f16.f32 "
        "{%0,%1,%2,%3}, {%4,%5,%6,%7}, {%8,%9}, {%0,%1,%2,%3};"
        : "+f"(c[0]), "+f"(c[1]), "+f"(c[2]), "+f"(c[3])
        : "r"(a0), "r"(a1), "r"(a2), "r"(a3), "r"(b0), "r"(b1));
}

static __device__ __forceinline__ void cp_async16cg(uint32_t dst, const void* src) {
    asm volatile("cp.async.cg.shared.global [%0], [%1], 16;"
                 :: "r"(dst), "l"(src) : "memory");
}

static __device__ __forceinline__ void lds128(uint32_t& r0, uint32_t& r1,
                                              uint32_t& r2, uint32_t& r3, uint32_t a) {
    asm volatile("ld.shared.v4.b32 {%0,%1,%2,%3}, [%4];"
                 : "=r"(r0), "=r"(r1), "=r"(r2), "=r"(r3) : "r"(a));
}

static __device__ __forceinline__ void sts32(uint32_t addr, uint32_t v) {
    asm volatile("st.shared.b32 [%0], %1;" :: "r"(addr), "r"(v) : "memory");
}

// ============================================================================
__global__ __launch_bounds__(256, 2) void shiftconv_mma(
    const float* __restrict__ x,
    const float* __restrict__ bias,
    const int* __restrict__ shift_h,
    const int* __restrict__ shift_w,
    float* __restrict__ out)
{
    extern __shared__ float smem[];
    // [A0 f4 | A1 f4 | B0 f4 | B1 f4 | shw 256 | bias 256]
    float* A0_p   = smem;
    float* B0_p   = smem + 8 * A_F4;
    int*   shw_s  = (int*)(smem + 8 * A_F4 + 8 * B_F4);
    float* bias_s = (float*)(shw_s + 256);

    int tid  = threadIdx.x;
    int lane = tid & 31;
    int warp_n = tid >> 5;       // 8 N-warps (32 cols each); all span M 0..63

    shw_s[tid]  = (shift_h[tid] << 16) | (shift_w[tid] & 0xffff);
    bias_s[tid] = bias[tid];

    int m0   = blockIdx.x * 64;
    int nimg = m0 >> 12;
    int pix0 = m0 & 4095;
    int yrow = pix0 >> 6;        // one image row per CTA
    const float* xb = x + (size_t)nimg * (CIN * HW);

    // gather ownership: pixel mloc (0..63), channel octet kg (0..3)
    int mloc = tid & 63;
    int kg   = tid >> 6;

    // A staging pieces
    int sks   = kg >> 1;
    int sw_w  = (kg & 1) * 2 + ((mloc >> 3) & 1);   // word index in f4 slot
    int sg    = mloc >> 4;
    int sr    = mloc & 7;
    int sswz  = (sr >> 1) & 3;

    uint32_t a_smem[2], b_smem[2];
    a_smem[0] = (uint32_t)__cvta_generic_to_shared(A0_p);
    a_smem[1] = a_smem[0] + A_F4 * 16;
    b_smem[0] = (uint32_t)__cvta_generic_to_shared(B0_p);
    b_smem[1] = b_smem[0] + B_F4 * 16;

    // A layout bytes: ks*2048 + g*512 + r*64 + a*16 + word*4
    uint32_t sts_base = (uint32_t)(sks * 2048 + sg * 512 + sr * 64 + sw_w * 4);

    __syncthreads();

    #define CP_B(s_, buf) do {                                                 \
        const float4* src = g_wp + (size_t)(s_) * B_F4;                        \
        _Pragma("unroll")                                                      \
        for (int it = 0; it < 4; ++it) {                                       \
            int g = it * 256 + tid;                                            \
            cp_async16cg(b_smem[buf] + (uint32_t)g * 16, src + g);             \
        }                                                                      \
        asm volatile("cp.async.commit_group;" ::: "memory");                   \
    } while (0)

    #define GATHER_A(c0, regs) do {                                            \
        _Pragma("unroll")                                                      \
        for (int i = 0; i < 8; ++i) {                                          \
            int c  = (c0) + kg * 8 + i;                                        \
            int w_ = shw_s[c];                                                 \
            int sy = yrow + (w_ >> 16);                                        \
            int sx = mloc + ((w_ << 16) >> 16);                                \
            float v = 0.f;                                                     \
            if ((unsigned)sy < 64u && (unsigned)sx < 64u)                      \
                v = __ldg(xb + (size_t)c * HW + sy * 64 + sx);                 \
            regs[i] = v;                                                       \
        }                                                                      \
    } while (0)

    // 4 STS.32: word sw_w of f4 slot (sks, sg, sr, a^sswz), a = 0..3
    #define STS_A(regs, buf) do {                                              \
        uint32_t base = a_smem[buf] + sts_base;                                \
        _Pragma("unroll")                                                      \
        for (int a = 0; a < 4; ++a)                                            \
            sts32(base + (uint32_t)((a ^ sswz) * 16),                          \
                  f16x2(regs[2 * a + 1], regs[2 * a]));                        \
    } while (0)

    float acc[4][4][4];
    #pragma unroll
    for (int mt = 0; mt < 4; ++mt)
        #pragma unroll
        for (int nt = 0; nt < 4; ++nt)
            #pragma unroll
            for (int e = 0; e < 4; ++e) acc[mt][nt][e] = 0.f;

    // ---- prologue ----
    {
        CP_B(0, 0);
        float regs[8];
        GATHER_A(0, regs);
        STS_A(regs, 0);
        asm volatile("cp.async.wait_group 0;" ::: "memory");
        __syncthreads();
    }

    // ---- per-thread fragment bases (swizzles thread-constant) ----
    int fa = lane & 3;
    int fr = lane >> 2;
    uint32_t fswz = (uint32_t)((fa ^ ((fr >> 1) & 3)) * 16);
    uint32_t a_tbase = (uint32_t)(fr * 64) + fswz;              // + ks*2048 + mt*512
    uint32_t b_tbase = (uint32_t)((warp_n * 32 + fr) * 64) + fswz;  // + nt*512

    // ---- mainloop: 8 chunks of K=32 ----
    for (int s = 0; s < NCH; ++s) {
        int b = s & 1;
        float pregs[8];
        if (s < NCH - 1) {
            CP_B(s + 1, b ^ 1);
            GATHER_A((s + 1) * 32, pregs);   // LDGs overlap compute
        }

        // B fragments: one LDS.128 per nt covers BOTH k-steps
        uint32_t bf[4][4];
        #pragma unroll
        for (int nt = 0; nt < 4; ++nt)
            lds128(bf[nt][0], bf[nt][1], bf[nt][2], bf[nt][3],
                   b_smem[b] + b_tbase + (uint32_t)(nt * 512));

        #pragma unroll
        for (int ks = 0; ks < 2; ++ks) {
            uint32_t af[4][4];
            #pragma unroll
            for (int mt = 0; mt < 4; ++mt)
                lds128(af[mt][0], af[mt][1], af[mt][2], af[mt][3],
                       a_smem[b] + a_tbase + (uint32_t)(ks * 2048 + mt * 512));
            #pragma unroll
            for (int mt = 0; mt < 4; ++mt)
                #pragma unroll
                for (int nt = 0; nt < 4; ++nt)
                    mma_f16(acc[mt][nt],
                            af[mt][0], af[mt][1], af[mt][2], af[mt][3],
                            bf[nt][2 * ks], bf[nt][2 * ks + 1]);
        }

        if (s < NCH - 1) STS_A(pregs, b ^ 1);
        asm volatile("cp.async.wait_group 0;" ::: "memory");
        __syncthreads();
    }

    // ---- epilogue: bias + store out[n][d][pixel] ----
    float* ob = out + (size_t)nimg * (NOUT * HW) + pix0;
    #pragma unroll
    for (int mt = 0; mt < 4; ++mt) {
        int m_ = mt * 16 + (lane >> 2);
        #pragma unroll
        for (int nt = 0; nt < 4; ++nt) {
            int d_ = warp_n * 32 + nt * 8 + 2 * (lane & 3);
            float b0 = bias_s[d_], b1 = bias_s[d_ + 1];
            size_t o = (size_t)d_ * HW + m_;
            ob[o]          = acc[mt][nt][0] + b0;
            ob[o + HW]     = acc[mt][nt][1] + b1;
            ob[o + 8]      = acc[mt][nt][2] + b0;
            ob[o + HW + 8] = acc[mt][nt][3] + b1;
        }
    }

    #undef CP_B
    #undef GATHER_A
    #undef STS_A
}

// ============================================================================
extern "C" void kernel_launch(void* const* d_in, const int* in_sizes, int n_in,
                              void* d_out, int out_size) {
    const float* x      = (const float*)d_in[0];
    const float* weight = (const float*)d_in[1];
    const float* bias   = (const float*)d_in[2];
    const int*   sh     = (const int*)d_in[3];
    const int*   sw     = (const int*)d_in[4];
    float*       out    = (float*)d_out;

    // A 2x4KB + B 2x16KB + tables 2KB = 43008 B per CTA -> 2 CTAs/SM
    const int smem_bytes = (2 * A_F4 + 2 * B_F4) * 16 + 2 * 256 * 4;
    static int attr_set = 0;
    if (!attr_set) {
        cudaFuncSetAttribute(shiftconv_mma,
                             cudaFuncAttributeMaxDynamicSharedMemorySize, smem_bytes);
        cudaFuncSetAttribute(shiftconv_mma,
                             cudaFuncAttributePreferredSharedMemoryCarveout, 100);
        attr_set = 1;
    }

    pack_w_kernel<<<32, 256>>>(weight);
    // 131072 pixels / 64 per CTA = 2048 CTAs
    shiftconv_mma<<<2048, 256, smem_bytes>>>(x, bias, sh, sw, out);
}

// round 9
// speedup vs baseline: 1.0608x; 1.0608x over previous
#include <cuda_runtime.h>
#include <cstdint>

// ============================================================================
// ShiftConv as gather-GEMM, fp16 mma.sync m16n8k16 (fp32 accum):
//   out[n,d,y,x] = sum_c x[n,c,y+sh[c],x+sw[c]] * W[c,d] + bias[d]
// M = 131072 pixels, K = 256, N = 256.
// CTA 128(M) x 256(N), 512 thr (16 warps, warp tile 64x32), K chunk 64 x 4,
// double-buffered; gather split into two halves interleaved with MMA blocks.
// ============================================================================

#define CIN   256
#define NOUT  256
#define HW    4096

// A stage: f4[4 ks][8 g][8 r][4 a'] = 1024 f4 = 16 KB / buffer
#define A_F4   1024
// B stage: 2 sections of f4[256 n][4 a'] = 2048 f4 = 32 KB / buffer
#define B_F4   2048
#define NCH    4             // chunks of K=64

__device__ float4 g_wp[8 * 1024];   // packed fp16 weight, 128 KB (8 x 32-ch groups)

static __device__ __forceinline__ uint32_t f16x2(float hi, float lo) {
    uint32_t d;
    asm("cvt.rn.f16x2.f32 %0, %1, %2;" : "=r"(d) : "f"(hi), "f"(lo));
    return d;
}

// --- prep: pack W into fp16 f4 slots, fragment-paired + pre-swizzled ---
// f4 index: s(8)|n(256)|a'(4); a = a' ^ ((n>>1)&3); c0 = s*32 + a*2
// words: w0={W[c0],W[c0+1]}, w1={+8,+9}, w2={+16,+17}, w3={+24,+25} (all @ n)
__global__ void pack_w_kernel(const float* __restrict__ w) {
    int t = blockIdx.x * 256 + threadIdx.x;     // 0..8191
    int ap = t & 3;
    int n  = (t >> 2) & 255;
    int s  = t >> 10;
    int a  = ap ^ ((n >> 1) & 3);
    int c0 = s * 32 + a * 2;
    float4 v;
    v.x = __uint_as_float(f16x2(w[(c0 +  1) * NOUT + n], w[(c0     ) * NOUT + n]));
    v.y = __uint_as_float(f16x2(w[(c0 +  9) * NOUT + n], w[(c0 +  8) * NOUT + n]));
    v.z = __uint_as_float(f16x2(w[(c0 + 17) * NOUT + n], w[(c0 + 16) * NOUT + n]));
    v.w = __uint_as_float(f16x2(w[(c0 + 25) * NOUT + n], w[(c0 + 24) * NOUT + n]));
    g_wp[t] = v;
}

static __device__ __forceinline__ void mma_f16(float* c, uint32_t a0, uint32_t a1,
                                               uint32_t a2, uint32_t a3,
                                               uint32_t b0, uint32_t b1) {
    asm volatile(
        "mma.sync.aligned.m16n8k16.row.col.f32.f16.f16.f32 "
        "{%0,%1,%2,%3}, {%4,%5,%6,%7}, {%8,%9}, {%0,%1,%2,%3};"
        : "+f"(c[0]), "+f"(c[1]), "+f"(c[2]), "+f"(c[3])
        : "r"(a0), "r"(a1), "r"(a2), "r"(a3), "r"(b0), "r"(b1));
}

static __device__ __forceinline__ void cp_async16cg(uint32_t dst, const void* src) {
    asm volatile("cp.async.cg.shared.global [%0], [%1], 16;"
                 :: "r"(dst), "l"(src) : "memory");
}

static __device__ __forceinline__ void lds128(uint32_t& r0, uint32_t& r1,
                                              uint32_t& r2, uint32_t& r3, uint32_t a) {
    asm volatile("ld.shared.v4.b32 {%0,%1,%2,%3}, [%4];"
                 : "=r"(r0), "=r"(r1), "=r"(r2), "=r"(r3) : "r"(a));
}

static __device__ __forceinline__ void sts32(uint32_t addr, uint32_t v) {
    asm volatile("st.shared.b32 [%0], %1;" :: "r"(addr), "r"(v) : "memory");
}

// ============================================================================
__global__ __launch_bounds__(512, 1) void shiftconv_mma(
    const float* __restrict__ x,
    const float* __restrict__ bias,
    const int* __restrict__ shift_h,
    const int* __restrict__ shift_w,
    float* __restrict__ out)
{
    extern __shared__ float smem[];
    // [A0 f4 | A1 f4 | B0 f4 | B1 f4 | shw 256 | bias 256]
    float* A0_p   = smem;
    float* B0_p   = smem + 8 * A_F4;
    int*   shw_s  = (int*)(smem + 8 * A_F4 + 8 * B_F4);
    float* bias_s = (float*)(shw_s + 256);

    int tid  = threadIdx.x;
    int lane = tid & 31;
    int wid  = tid >> 5;
    int warp_m = wid & 1;        // 2 M-warps (64 rows each)
    int warp_n = wid >> 1;       // 8 N-warps (32 cols each)

    if (tid < 256) {
        shw_s[tid]  = (shift_h[tid] << 16) | (shift_w[tid] & 0xffff);
        bias_s[tid] = bias[tid];
    }

    int m0   = blockIdx.x * 128;
    int nimg = m0 >> 12;
    int pix0 = m0 & 4095;
    const float* xb = x + (size_t)nimg * (CIN * HW);

    // gather ownership: pixel mloc (0..127), k-step group kg (0..3, 16 ch each)
    int mloc = tid & 127;
    int kg   = tid >> 7;
    int y    = (pix0 + mloc) >> 6;
    int xc   = mloc & 63;

    // A staging pieces: slot (ks=kg, g, r, a), word = o*2 + mhalf
    int sg    = mloc >> 4;
    int sr    = mloc & 7;
    int smh   = (mloc >> 3) & 1;
    int sswz  = (sr >> 1) & 3;

    uint32_t a_smem[2], b_smem[2];
    a_smem[0] = (uint32_t)__cvta_generic_to_shared(A0_p);
    a_smem[1] = a_smem[0] + A_F4 * 16;
    b_smem[0] = (uint32_t)__cvta_generic_to_shared(B0_p);
    b_smem[1] = b_smem[0] + B_F4 * 16;

    // A bytes: ks*4096 + g*512 + r*64 + a*16 + (o*2+mhalf)*4
    uint32_t sts_base = (uint32_t)(kg * 4096 + sg * 512 + sr * 64 + smh * 4);

    __syncthreads();

    #define CP_B(s_, buf) do {                                                 \
        const float4* src = g_wp + (size_t)(s_) * B_F4;                        \
        _Pragma("unroll")                                                      \
        for (int it = 0; it < 4; ++it) {                                       \
            int g = it * 512 + tid;                                            \
            cp_async16cg(b_smem[buf] + (uint32_t)g * 16, src + g);             \
        }                                                                      \
        asm volatile("cp.async.commit_group;" ::: "memory");                   \
    } while (0)

    // gather one octet (8 channels): c = c0 + kg*16 + o*8 + (2a, 2a+1)
    #define GATHER_O(c0, o, p) do {                                            \
        _Pragma("unroll")                                                      \
        for (int i = 0; i < 8; ++i) {                                          \
            int c  = (c0) + kg * 16 + (o) * 8 + i;                             \
            int w_ = shw_s[c];                                                 \
            int sy = y + (w_ >> 16);                                           \
            int sx = xc + ((w_ << 16) >> 16);                                  \
            float v = 0.f;                                                     \
            if ((unsigned)sy < 64u && (unsigned)sx < 64u)                      \
                v = __ldg(xb + (size_t)c * HW + sy * 64 + sx);                 \
            p[i] = v;                                                          \
        }                                                                      \
    } while (0)

    // store one octet: 4 STS.32 at word (o*2 + smh)
    #define STS_O(p, buf, o) do {                                              \
        uint32_t base = a_smem[buf] + sts_base + (uint32_t)((o) * 8);          \
        _Pragma("unroll")                                                      \
        for (int a = 0; a < 4; ++a)                                            \
            sts32(base + (uint32_t)((a ^ sswz) * 16),                          \
                  f16x2(p[2 * a + 1], p[2 * a]));                              \
    } while (0)

    float acc[4][4][4];
    #pragma unroll
    for (int mt = 0; mt < 4; ++mt)
        #pragma unroll
        for (int nt = 0; nt < 4; ++nt)
            #pragma unroll
            for (int e = 0; e < 4; ++e) acc[mt][nt][e] = 0.f;

    // ---- prologue: stage chunk 0 ----
    {
        CP_B(0, 0);
        float p[8];
        GATHER_O(0, 0, p);
        STS_O(p, 0, 0);
        GATHER_O(0, 1, p);
        STS_O(p, 0, 1);
        asm volatile("cp.async.wait_group 0;" ::: "memory");
        __syncthreads();
    }

    // ---- per-thread fragment bases (swizzles thread-constant) ----
    int fa = lane & 3;
    int fr = lane >> 2;
    uint32_t fswz = (uint32_t)((fa ^ ((fr >> 1) & 3)) * 16);
    uint32_t a_tbase = (uint32_t)(warp_m * 4 * 512 + fr * 64) + fswz;  // +ks*4096+mt*512
    uint32_t b_tbase = (uint32_t)((warp_n * 32 + fr) * 64) + fswz;    // +kss*16384+nt*512

    // ---- mainloop: 4 chunks of K=64 ----
    for (int s = 0; s < NCH; ++s) {
        int b = s & 1;
        float p[8];
        if (s < NCH - 1) {
            CP_B(s + 1, b ^ 1);
            GATHER_O((s + 1) * 64, 0, p);   // first octet LDGs in flight
        }

        #pragma unroll
        for (int kss = 0; kss < 2; ++kss) {
            // B fragments: one LDS.128 per nt covers both k-steps of section
            uint32_t bf[4][4];
            #pragma unroll
            for (int nt = 0; nt < 4; ++nt)
                lds128(bf[nt][0], bf[nt][1], bf[nt][2], bf[nt][3],
                       b_smem[b] + b_tbase + (uint32_t)(kss * 16384 + nt * 512));

            #pragma unroll
            for (int ksh = 0; ksh < 2; ++ksh) {
                int ks = kss * 2 + ksh;
                uint32_t af[4][4];
                #pragma unroll
                for (int mt = 0; mt < 4; ++mt)
                    lds128(af[mt][0], af[mt][1], af[mt][2], af[mt][3],
                           a_smem[b] + a_tbase + (uint32_t)(ks * 4096 + mt * 512));
                #pragma unroll
                for (int mt = 0; mt < 4; ++mt)
                    #pragma unroll
                    for (int nt = 0; nt < 4; ++nt)
                        mma_f16(acc[mt][nt],
                                af[mt][0], af[mt][1], af[mt][2], af[mt][3],
                                bf[nt][2 * ksh], bf[nt][2 * ksh + 1]);
            }

            // between the two MMA blocks: store octet 0, launch octet 1
            if (kss == 0 && s < NCH - 1) {
                STS_O(p, b ^ 1, 0);
                GATHER_O((s + 1) * 64, 1, p);
            }
        }

        if (s < NCH - 1) STS_O(p, b ^ 1, 1);
        asm volatile("cp.async.wait_group 0;" ::: "memory");
        __syncthreads();
    }

    // ---- epilogue: bias + store out[n][d][pixel] ----
    float* ob = out + (size_t)nimg * (NOUT * HW) + pix0;
    #pragma unroll
    for (int mt = 0; mt < 4; ++mt) {
        int m_ = warp_m * 64 + mt * 16 + (lane >> 2);
        #pragma unroll
        for (int nt = 0; nt < 4; ++nt) {
            int d_ = warp_n * 32 + nt * 8 + 2 * (lane & 3);
            float b0 = bias_s[d_], b1 = bias_s[d_ + 1];
            size_t o = (size_t)d_ * HW + m_;
            ob[o]          = acc[mt][nt][0] + b0;
            ob[o + HW]     = acc[mt][nt][1] + b1;
            ob[o + 8]      = acc[mt][nt][2] + b0;
            ob[o + HW + 8] = acc[mt][nt][3] + b1;
        }
    }

    #undef CP_B
    #undef GATHER_O
    #undef STS_O
}

// ============================================================================
extern "C" void kernel_launch(void* const* d_in, const int* in_sizes, int n_in,
                              void* d_out, int out_size) {
    const float* x      = (const float*)d_in[0];
    const float* weight = (const float*)d_in[1];
    const float* bias   = (const float*)d_in[2];
    const int*   sh     = (const int*)d_in[3];
    const int*   sw     = (const int*)d_in[4];
    float*       out    = (float*)d_out;

    // A 2x16KB + B 2x32KB + tables 2KB = 100352 B (1 CTA/SM)
    const int smem_bytes = (2 * A_F4 + 2 * B_F4) * 16 + 2 * 256 * 4;
    static int attr_set = 0;
    if (!attr_set) {
        cudaFuncSetAttribute(shiftconv_mma,
                             cudaFuncAttributeMaxDynamicSharedMemorySize, smem_bytes);
        attr_set = 1;
    }

    pack_w_kernel<<<32, 256>>>(weight);
    // 131072 pixels / 128 per CTA = 1024 CTAs
    shiftconv_mma<<<1024, 512, smem_bytes>>>(x, bias, sh, sw, out);
}

// round 10
// speedup vs baseline: 1.0611x; 1.0003x over previous
#include <cuda_runtime.h>
#include <cstdint>

// ============================================================================
// ShiftConv as gather-GEMM, fp16 mma.sync m16n8k16 (fp32 accum):
//   out[n,d,y,x] = sum_c x[n,c,y+sh[c],x+sw[c]] * W[c,d] + bias[d]
// M = 131072 pixels, K = 256, N = 256.
// CTA 128(M) x 256(N), 512 thr (16 warps, warp tile 64x32), K chunk 64 x 4,
// double-buffered; gather split into two halves interleaved with MMA blocks.
// ============================================================================

#define CIN   256
#define NOUT  256
#define HW    4096

// A stage: f4[4 ks][8 g][8 r][4 a'] = 1024 f4 = 16 KB / buffer
#define A_F4   1024
// B stage: 2 sections of f4[256 n][4 a'] = 2048 f4 = 32 KB / buffer
#define B_F4   2048
#define NCH    4             // chunks of K=64

__device__ float4 g_wp[8 * 1024];   // packed fp16 weight, 128 KB (8 x 32-ch groups)

static __device__ __forceinline__ uint32_t f16x2(float hi, float lo) {
    uint32_t d;
    asm("cvt.rn.f16x2.f32 %0, %1, %2;" : "=r"(d) : "f"(hi), "f"(lo));
    return d;
}

// --- prep: pack W into fp16 f4 slots, fragment-paired + pre-swizzled ---
// f4 index: s(8)|n(256)|a'(4); a = a' ^ ((n>>1)&3); c0 = s*32 + a*2
// words: w0={W[c0],W[c0+1]}, w1={+8,+9}, w2={+16,+17}, w3={+24,+25} (all @ n)
__global__ void pack_w_kernel(const float* __restrict__ w) {
    int t = blockIdx.x * 256 + threadIdx.x;     // 0..8191
    int ap = t & 3;
    int n  = (t >> 2) & 255;
    int s  = t >> 10;
    int a  = ap ^ ((n >> 1) & 3);
    int c0 = s * 32 + a * 2;
    float4 v;
    v.x = __uint_as_float(f16x2(w[(c0 +  1) * NOUT + n], w[(c0     ) * NOUT + n]));
    v.y = __uint_as_float(f16x2(w[(c0 +  9) * NOUT + n], w[(c0 +  8) * NOUT + n]));
    v.z = __uint_as_float(f16x2(w[(c0 + 17) * NOUT + n], w[(c0 + 16) * NOUT + n]));
    v.w = __uint_as_float(f16x2(w[(c0 + 25) * NOUT + n], w[(c0 + 24) * NOUT + n]));
    g_wp[t] = v;
}

static __device__ __forceinline__ void mma_f16(float* c, uint32_t a0, uint32_t a1,
                                               uint32_t a2, uint32_t a3,
                                               uint32_t b0, uint32_t b1) {
    asm volatile(
        "mma.sync.aligned.m16n8k16.row.col.f32.f16.f16.f32 "
        "{%0,%1,%2,%3}, {%4,%5,%6,%7}, {%8,%9}, {%0,%1,%2,%3};"
        : "+f"(c[0]), "+f"(c[1]), "+f"(c[2]), "+f"(c[3])
        : "r"(a0), "r"(a1), "r"(a2), "r"(a3), "r"(b0), "r"(b1));
}

static __device__ __forceinline__ void cp_async16cg(uint32_t dst, const void* src) {
    asm volatile("cp.async.cg.shared.global [%0], [%1], 16;"
                 :: "r"(dst), "l"(src) : "memory");
}

static __device__ __forceinline__ void lds128(uint32_t& r0, uint32_t& r1,
                                              uint32_t& r2, uint32_t& r3, uint32_t a) {
    asm volatile("ld.shared.v4.b32 {%0,%1,%2,%3}, [%4];"
                 : "=r"(r0), "=r"(r1), "=r"(r2), "=r"(r3) : "r"(a));
}

static __device__ __forceinline__ void sts32(uint32_t addr, uint32_t v) {
    asm volatile("st.shared.b32 [%0], %1;" :: "r"(addr), "r"(v) : "memory");
}

// ============================================================================
__global__ __launch_bounds__(512, 1) void shiftconv_mma(
    const float* __restrict__ x,
    const float* __restrict__ bias,
    const int* __restrict__ shift_h,
    const int* __restrict__ shift_w,
    float* __restrict__ out)
{
    extern __shared__ float smem[];
    // [A0 f4 | A1 f4 | B0 f4 | B1 f4 | shw 256 | bias 256]
    float* A0_p   = smem;
    float* B0_p   = smem + 8 * A_F4;
    int*   shw_s  = (int*)(smem + 8 * A_F4 + 8 * B_F4);
    float* bias_s = (float*)(shw_s + 256);

    int tid  = threadIdx.x;
    int lane = tid & 31;
    int wid  = tid >> 5;
    int warp_m = wid & 1;        // 2 M-warps (64 rows each)
    int warp_n = wid >> 1;       // 8 N-warps (32 cols each)

    if (tid < 256) {
        shw_s[tid]  = (shift_h[tid] << 16) | (shift_w[tid] & 0xffff);
        bias_s[tid] = bias[tid];
    }

    int m0   = blockIdx.x * 128;
    int nimg = m0 >> 12;
    int pix0 = m0 & 4095;
    const float* xb = x + (size_t)nimg * (CIN * HW);

    // gather ownership: pixel mloc (0..127), k-step group kg (0..3, 16 ch each)
    int mloc = tid & 127;
    int kg   = tid >> 7;
    int y    = (pix0 + mloc) >> 6;
    int xc   = mloc & 63;

    // A staging pieces: slot (ks=kg, g, r, a), word = o*2 + mhalf
    int sg    = mloc >> 4;
    int sr    = mloc & 7;
    int smh   = (mloc >> 3) & 1;
    int sswz  = (sr >> 1) & 3;

    uint32_t a_smem[2], b_smem[2];
    a_smem[0] = (uint32_t)__cvta_generic_to_shared(A0_p);
    a_smem[1] = a_smem[0] + A_F4 * 16;
    b_smem[0] = (uint32_t)__cvta_generic_to_shared(B0_p);
    b_smem[1] = b_smem[0] + B_F4 * 16;

    // A bytes: ks*4096 + g*512 + r*64 + a*16 + (o*2+mhalf)*4
    uint32_t sts_base = (uint32_t)(kg * 4096 + sg * 512 + sr * 64 + smh * 4);

    __syncthreads();

    #define CP_B(s_, buf) do {                                                 \
        const float4* src = g_wp + (size_t)(s_) * B_F4;                        \
        _Pragma("unroll")                                                      \
        for (int it = 0; it < 4; ++it) {                                       \
            int g = it * 512 + tid;                                            \
            cp_async16cg(b_smem[buf] + (uint32_t)g * 16, src + g);             \
        }                                                                      \
        asm volatile("cp.async.commit_group;" ::: "memory");                   \
    } while (0)

    // gather one octet (8 channels): c = c0 + kg*16 + o*8 + (2a, 2a+1)
    #define GATHER_O(c0, o, p) do {                                            \
        _Pragma("unroll")                                                      \
        for (int i = 0; i < 8; ++i) {                                          \
            int c  = (c0) + kg * 16 + (o) * 8 + i;                             \
            int w_ = shw_s[c];                                                 \
            int sy = y + (w_ >> 16);                                           \
            int sx = xc + ((w_ << 16) >> 16);                                  \
            float v = 0.f;                                                     \
            if ((unsigned)sy < 64u && (unsigned)sx < 64u)                      \
                v = __ldg(xb + (size_t)c * HW + sy * 64 + sx);                 \
            p[i] = v;                                                          \
        }                                                                      \
    } while (0)

    // store one octet: 4 STS.32 at word (o*2 + smh)
    #define STS_O(p, buf, o) do {                                              \
        uint32_t base = a_smem[buf] + sts_base + (uint32_t)((o) * 8);          \
        _Pragma("unroll")                                                      \
        for (int a = 0; a < 4; ++a)                                            \
            sts32(base + (uint32_t)((a ^ sswz) * 16),                          \
                  f16x2(p[2 * a + 1], p[2 * a]));                              \
    } while (0)

    float acc[4][4][4];
    #pragma unroll
    for (int mt = 0; mt < 4; ++mt)
        #pragma unroll
        for (int nt = 0; nt < 4; ++nt)
            #pragma unroll
            for (int e = 0; e < 4; ++e) acc[mt][nt][e] = 0.f;

    // ---- prologue: stage chunk 0 ----
    {
        CP_B(0, 0);
        float p[8];
        GATHER_O(0, 0, p);
        STS_O(p, 0, 0);
        GATHER_O(0, 1, p);
        STS_O(p, 0, 1);
        asm volatile("cp.async.wait_group 0;" ::: "memory");
        __syncthreads();
    }

    // ---- per-thread fragment bases (swizzles thread-constant) ----
    int fa = lane & 3;
    int fr = lane >> 2;
    uint32_t fswz = (uint32_t)((fa ^ ((fr >> 1) & 3)) * 16);
    uint32_t a_tbase = (uint32_t)(warp_m * 4 * 512 + fr * 64) + fswz;  // +ks*4096+mt*512
    uint32_t b_tbase = (uint32_t)((warp_n * 32 + fr) * 64) + fswz;    // +kss*16384+nt*512

    // ---- mainloop: 4 chunks of K=64 ----
    for (int s = 0; s < NCH; ++s) {
        int b = s & 1;
        float p[8];
        if (s < NCH - 1) {
            CP_B(s + 1, b ^ 1);
            GATHER_O((s + 1) * 64, 0, p);   // first octet LDGs in flight
        }

        #pragma unroll
        for (int kss = 0; kss < 2; ++kss) {
            // B fragments: one LDS.128 per nt covers both k-steps of section
            uint32_t bf[4][4];
            #pragma unroll
            for (int nt = 0; nt < 4; ++nt)
                lds128(bf[nt][0], bf[nt][1], bf[nt][2], bf[nt][3],
                       b_smem[b] + b_tbase + (uint32_t)(kss * 16384 + nt * 512));

            #pragma unroll
            for (int ksh = 0; ksh < 2; ++ksh) {
                int ks = kss * 2 + ksh;
                uint32_t af[4][4];
                #pragma unroll
                for (int mt = 0; mt < 4; ++mt)
                    lds128(af[mt][0], af[mt][1], af[mt][2], af[mt][3],
                           a_smem[b] + a_tbase + (uint32_t)(ks * 4096 + mt * 512));
                #pragma unroll
                for (int mt = 0; mt < 4; ++mt)
                    #pragma unroll
                    for (int nt = 0; nt < 4; ++nt)
                        mma_f16(acc[mt][nt],
                                af[mt][0], af[mt][1], af[mt][2], af[mt][3],
                                bf[nt][2 * ksh], bf[nt][2 * ksh + 1]);
            }

            // between the two MMA blocks: store octet 0, launch octet 1
            if (kss == 0 && s < NCH - 1) {
                STS_O(p, b ^ 1, 0);
                GATHER_O((s + 1) * 64, 1, p);
            }
        }

        if (s < NCH - 1) STS_O(p, b ^ 1, 1);
        asm volatile("cp.async.wait_group 0;" ::: "memory");
        __syncthreads();
    }

    // ---- epilogue: bias + store out[n][d][pixel] ----
    float* ob = out + (size_t)nimg * (NOUT * HW) + pix0;
    #pragma unroll
    for (int mt = 0; mt < 4; ++mt) {
        int m_ = warp_m * 64 + mt * 16 + (lane >> 2);
        #pragma unroll
        for (int nt = 0; nt < 4; ++nt) {
            int d_ = warp_n * 32 + nt * 8 + 2 * (lane & 3);
            float b0 = bias_s[d_], b1 = bias_s[d_ + 1];
            size_t o = (size_t)d_ * HW + m_;
            ob[o]          = acc[mt][nt][0] + b0;
            ob[o + HW]     = acc[mt][nt][1] + b1;
            ob[o + 8]      = acc[mt][nt][2] + b0;
            ob[o + HW + 8] = acc[mt][nt][3] + b1;
        }
    }

    #undef CP_B
    #undef GATHER_O
    #undef STS_O
}

// ============================================================================
extern "C" void kernel_launch(void* const* d_in, const int* in_sizes, int n_in,
                              void* d_out, int out_size) {
    const float* x      = (const float*)d_in[0];
    const float* weight = (const float*)d_in[1];
    const float* bias   = (const float*)d_in[2];
    const int*   sh     = (const int*)d_in[3];
    const int*   sw     = (const int*)d_in[4];
    float*       out    = (float*)d_out;

    // A 2x16KB + B 2x32KB + tables 2KB = 100352 B (1 CTA/SM)
    const int smem_bytes = (2 * A_F4 + 2 * B_F4) * 16 + 2 * 256 * 4;
    static int attr_set = 0;
    if (!attr_set) {
        cudaFuncSetAttribute(shiftconv_mma,
                             cudaFuncAttributeMaxDynamicSharedMemorySize, smem_bytes);
        attr_set = 1;
    }

    pack_w_kernel<<<32, 256>>>(weight);
    // 131072 pixels / 128 per CTA = 1024 CTAs
    shiftconv_mma<<<1024, 512, smem_bytes>>>(x, bias, sh, sw, out);
}

// round 11
// speedup vs baseline: 1.1615x; 1.0946x over previous
#include <cuda_runtime.h>
#include <cstdint>

// ============================================================================
// ShiftConv as gather-GEMM, fp16 mma.sync m16n8k16 (fp32 accum):
//   out[n,d,y,x] = sum_c x[n,c,y+sh[c],x+sw[c]] * W[c,d] + bias[d]
// M = 131072 pixels, K = 256, N = 256.
// PERSISTENT: 148 CTAs, each loops over ~7 M-tiles of 128 pixels.
// B (256x256 fp16 = 128 KB) resident in smem for the CTA lifetime.
// A: 3-buffer ring (8 KB each), gather pipelined 2 chunks ahead.
// 512 thr (16 warps, warp tile 64x32), K chunk 32 x 8.
// ============================================================================

#define CIN   256
#define NOUT  256
#define HW    4096
#define NTILE 1024           // 131072 / 128
#define GRID  148

// B resident: f4[8 s][256 n][4 a'] = 8192 f4 = 131072 B
// A ring:     3 x f4[2 ks][8 g][8 r][4 a'] = 3 x 512 f4 = 24576 B
#define B_BYTES  131072
#define A_BYTES  8192
#define SMEM_BYTES (B_BYTES + 3 * A_BYTES + 2 * 256 * 4)   // 157696

__device__ float4 g_wp[8192];   // packed fp16 weight, 128 KB

static __device__ __forceinline__ uint32_t f16x2(float hi, float lo) {
    uint32_t d;
    asm("cvt.rn.f16x2.f32 %0, %1, %2;" : "=r"(d) : "f"(hi), "f"(lo));
    return d;
}

// --- prep: pack W into fp16 f4 slots, fragment-paired + pre-swizzled ---
// f4 index: s(8)|n(256)|a'(4); a = a' ^ ((n>>1)&3); c0 = s*32 + a*2
// words: w0={W[c0],W[c0+1]}, w1={+8,+9}, w2={+16,+17}, w3={+24,+25} (all @ n)
__global__ void pack_w_kernel(const float* __restrict__ w) {
    int t = blockIdx.x * 256 + threadIdx.x;     // 0..8191
    int ap = t & 3;
    int n  = (t >> 2) & 255;
    int s  = t >> 10;
    int a  = ap ^ ((n >> 1) & 3);
    int c0 = s * 32 + a * 2;
    float4 v;
    v.x = __uint_as_float(f16x2(w[(c0 +  1) * NOUT + n], w[(c0     ) * NOUT + n]));
    v.y = __uint_as_float(f16x2(w[(c0 +  9) * NOUT + n], w[(c0 +  8) * NOUT + n]));
    v.z = __uint_as_float(f16x2(w[(c0 + 17) * NOUT + n], w[(c0 + 16) * NOUT + n]));
    v.w = __uint_as_float(f16x2(w[(c0 + 25) * NOUT + n], w[(c0 + 24) * NOUT + n]));
    g_wp[t] = v;
}

static __device__ __forceinline__ void mma_f16(float* c, uint32_t a0, uint32_t a1,
                                               uint32_t a2, uint32_t a3,
                                               uint32_t b0, uint32_t b1) {
    asm volatile(
        "mma.sync.aligned.m16n8k16.row.col.f32.f16.f16.f32 "
        "{%0,%1,%2,%3}, {%4,%5,%6,%7}, {%8,%9}, {%0,%1,%2,%3};"
        : "+f"(c[0]), "+f"(c[1]), "+f"(c[2]), "+f"(c[3])
        : "r"(a0), "r"(a1), "r"(a2), "r"(a3), "r"(b0), "r"(b1));
}

static __device__ __forceinline__ void cp_async16cg(uint32_t dst, const void* src) {
    asm volatile("cp.async.cg.shared.global [%0], [%1], 16;"
                 :: "r"(dst), "l"(src) : "memory");
}

static __device__ __forceinline__ void lds128(uint32_t& r0, uint32_t& r1,
                                              uint32_t& r2, uint32_t& r3, uint32_t a) {
    asm volatile("ld.shared.v4.b32 {%0,%1,%2,%3}, [%4];"
                 : "=r"(r0), "=r"(r1), "=r"(r2), "=r"(r3) : "r"(a));
}

static __device__ __forceinline__ void sts32(uint32_t addr, uint32_t v) {
    asm volatile("st.shared.b32 [%0], %1;" :: "r"(addr), "r"(v) : "memory");
}

// ============================================================================
__global__ __launch_bounds__(512, 1) void shiftconv_mma(
    const float* __restrict__ x,
    const float* __restrict__ bias,
    const int* __restrict__ shift_h,
    const int* __restrict__ shift_w,
    float* __restrict__ out)
{
    extern __shared__ float smem[];
    // [B 128KB | A ring 3x8KB | shw 256 | bias 256]
    int*   shw_s  = (int*)(smem + (B_BYTES + 3 * A_BYTES) / 4);
    float* bias_s = (float*)(shw_s + 256);

    int tid  = threadIdx.x;
    int lane = tid & 31;
    int wid  = tid >> 5;
    int warp_m = wid & 1;        // 2 M-warps (64 rows each)
    int warp_n = wid >> 1;       // 8 N-warps (32 cols each)

    if (tid < 256) {
        shw_s[tid]  = (shift_h[tid] << 16) | (shift_w[tid] & 0xffff);
        bias_s[tid] = bias[tid];
    }

    uint32_t b_smem = (uint32_t)__cvta_generic_to_shared(smem);
    uint32_t a_smem = b_smem + B_BYTES;

    // ---- load ALL of B once (128 KB, 16 cp.async per thread) ----
    #pragma unroll
    for (int it = 0; it < 16; ++it) {
        int g = it * 512 + tid;
        cp_async16cg(b_smem + (uint32_t)g * 16, g_wp + g);
    }
    asm volatile("cp.async.commit_group;" ::: "memory");

    // gather ownership: pixel mloc (0..127), channel octet kg (0..3)
    int mloc = tid & 127;
    int kg   = tid >> 7;
    int xc   = mloc & 63;

    // A staging pieces (R7 layout): bytes = ks*4096 + g*512 + r*64 + a*16 + w*4
    int sks   = kg >> 1;
    int sw_w  = (kg & 1) * 2 + ((mloc >> 3) & 1);
    int sg    = mloc >> 4;
    int sr    = mloc & 7;
    int sswz  = (sr >> 1) & 3;
    uint32_t sts_base = (uint32_t)(sks * 4096 + sg * 512 + sr * 64 + sw_w * 4);

    // fragment bases (thread-constant swizzles)
    int fa = lane & 3;
    int fr = lane >> 2;
    uint32_t fswz = (uint32_t)((fa ^ ((fr >> 1) & 3)) * 16);
    uint32_t a_tbase = (uint32_t)(warp_m * 4 * 512 + fr * 64) + fswz;
    uint32_t b_tbase = (uint32_t)((warp_n * 32 + fr) * 64) + fswz;

    #define GATHER(c0, p) do {                                                 \
        _Pragma("unroll")                                                      \
        for (int i = 0; i < 8; ++i) {                                          \
            int c  = (c0) + kg * 8 + i;                                        \
            int w_ = shw_s[c];                                                 \
            int sy = y + (w_ >> 16);                                           \
            int sx = xc + ((w_ << 16) >> 16);                                  \
            float v = 0.f;                                                     \
            if ((unsigned)sy < 64u && (unsigned)sx < 64u)                      \
                v = __ldg(xb + (size_t)c * HW + sy * 64 + sx);                 \
            p[i] = v;                                                          \
        }                                                                      \
    } while (0)

    #define STS_A(p, buf) do {                                                 \
        uint32_t base = a_smem + (uint32_t)((buf) * A_BYTES) + sts_base;       \
        _Pragma("unroll")                                                      \
        for (int a = 0; a < 4; ++a)                                            \
            sts32(base + (uint32_t)((a ^ sswz) * 16),                          \
                  f16x2(p[2 * a + 1], p[2 * a]));                              \
    } while (0)

    asm volatile("cp.async.wait_group 0;" ::: "memory");
    __syncthreads();   // B resident + tables ready

    // ======================= persistent tile loop =======================
    for (int t = blockIdx.x; t < NTILE; t += GRID) {
        int m0   = t << 7;
        int nimg = m0 >> 12;
        int pix0 = m0 & 4095;
        int y    = (pix0 + mloc) >> 6;
        const float* xb = x + (size_t)nimg * (CIN * HW);

        float acc[4][4][4];
        #pragma unroll
        for (int mt = 0; mt < 4; ++mt)
            #pragma unroll
            for (int nt = 0; nt < 4; ++nt)
                #pragma unroll
                for (int e = 0; e < 4; ++e) acc[mt][nt][e] = 0.f;

        // prologue: gather chunks 0 and 1, store chunk 0
        float p[2][8];
        GATHER(0,  p[0]);
        GATHER(32, p[1]);
        STS_A(p[0], 0);
        __syncthreads();

        // mainloop: 8 chunks of K=32, A ring of 3, gather 2 ahead
        #pragma unroll
        for (int s = 0; s < 8; ++s) {
            if (s < 7) STS_A(p[(s + 1) & 1], (s + 1) % 3);
            if (s < 6) GATHER((s + 2) * 32, p[s & 1]);

            uint32_t a_base = a_smem + (uint32_t)((s % 3) * A_BYTES);
            uint32_t b_base = b_smem + (uint32_t)(s * 16384);

            uint32_t bf[4][4];
            #pragma unroll
            for (int nt = 0; nt < 4; ++nt)
                lds128(bf[nt][0], bf[nt][1], bf[nt][2], bf[nt][3],
                       b_base + b_tbase + (uint32_t)(nt * 512));

            #pragma unroll
            for (int ks = 0; ks < 2; ++ks) {
                uint32_t af[4][4];
                #pragma unroll
                for (int mt = 0; mt < 4; ++mt)
                    lds128(af[mt][0], af[mt][1], af[mt][2], af[mt][3],
                           a_base + a_tbase + (uint32_t)(ks * 4096 + mt * 512));
                #pragma unroll
                for (int mt = 0; mt < 4; ++mt)
                    #pragma unroll
                    for (int nt = 0; nt < 4; ++nt)
                        mma_f16(acc[mt][nt],
                                af[mt][0], af[mt][1], af[mt][2], af[mt][3],
                                bf[nt][2 * ks], bf[nt][2 * ks + 1]);
            }
            __syncthreads();
        }

        // epilogue: bias + store out[n][d][pixel]
        float* ob = out + (size_t)nimg * (NOUT * HW) + pix0;
        #pragma unroll
        for (int mt = 0; mt < 4; ++mt) {
            int m_ = warp_m * 64 + mt * 16 + (lane >> 2);
            #pragma unroll
            for (int nt = 0; nt < 4; ++nt) {
                int d_ = warp_n * 32 + nt * 8 + 2 * (lane & 3);
                float b0 = bias_s[d_], b1 = bias_s[d_ + 1];
                size_t o = (size_t)d_ * HW + m_;
                ob[o]          = acc[mt][nt][0] + b0;
                ob[o + HW]     = acc[mt][nt][1] + b1;
                ob[o + 8]      = acc[mt][nt][2] + b0;
                ob[o + HW + 8] = acc[mt][nt][3] + b1;
            }
        }
    }

    #undef GATHER
    #undef STS_A
}

// ============================================================================
extern "C" void kernel_launch(void* const* d_in, const int* in_sizes, int n_in,
                              void* d_out, int out_size) {
    const float* x      = (const float*)d_in[0];
    const float* weight = (const float*)d_in[1];
    const float* bias   = (const float*)d_in[2];
    const int*   sh     = (const int*)d_in[3];
    const int*   sw     = (const int*)d_in[4];
    float*       out    = (float*)d_out;

    static int attr_set = 0;
    if (!attr_set) {
        cudaFuncSetAttribute(shiftconv_mma,
                             cudaFuncAttributeMaxDynamicSharedMemorySize, SMEM_BYTES);
        attr_set = 1;
    }

    pack_w_kernel<<<32, 256>>>(weight);
    shiftconv_mma<<<GRID, 512, SMEM_BYTES>>>(x, bias, sh, sw, out);
}